// round 9
// baseline (speedup 1.0000x reference)
#include <cuda_runtime.h>
#include <math.h>
#include <stdint.h>

#define NN 8192
#define FD 256
#define KSPLIT 2

// ---------------- scratch ----------------
__device__ float g_Wh[NN*FD];
__device__ float g_Whr[NN*FD];     // tf32-rounded Wh (attention B operand, cp.async source)
__device__ float g_s[NN], g_dv[NN], g_eS[NN], g_eS2[NN], g_eD[NN], g_eD2[NN];
__device__ float g_attn[NN*FD];
__device__ float g_attp[KSPLIT*NN*FD];
__device__ float g_rsp[KSPLIT*NN];
__device__ float g_bcdt[NN*384];
__device__ float g_asmb[NN*128];
__device__ float g_cv[NN];
__device__ float g_ab[NN*FD];
__device__ float g_hz[NN*1024];
__device__ float g_u[NN*512];
__device__ float g_hs[NN*FD];
__device__ float g_enh[NN*FD];
__device__ float g_fe[NN*512];
__device__ float g_gt[NN*512];
__device__ float g_gate[NN*FD];

// ---------------- helpers ----------------
__device__ __forceinline__ uint32_t f2tf32(float v) {
    uint32_t r;
    asm("cvt.rna.tf32.f32 %0, %1;" : "=r"(r) : "f"(v));
    return r;
}
__device__ __forceinline__ void mma_tf32(float* c, const uint32_t* a, const uint32_t* b) {
    asm volatile(
        "mma.sync.aligned.m16n8k8.row.col.f32.tf32.tf32.f32 "
        "{%0,%1,%2,%3}, {%4,%5,%6,%7}, {%8,%9}, {%0,%1,%2,%3};"
        : "+f"(c[0]), "+f"(c[1]), "+f"(c[2]), "+f"(c[3])
        : "r"(a[0]), "r"(a[1]), "r"(a[2]), "r"(a[3]), "r"(b[0]), "r"(b[1]));
}
__device__ __forceinline__ uint32_t smem_u32(const void* p) {
    uint32_t a;
    asm("{ .reg .u64 t; cvta.to.shared.u64 t, %1; cvt.u32.u64 %0, t; }" : "=r"(a) : "l"(p));
    return a;
}
__device__ __forceinline__ void cpasync16(uint32_t dst, const void* src) {
    asm volatile("cp.async.cg.shared.global [%0], [%1], 16;" :: "r"(dst), "l"(src));
}
#define CP_COMMIT() asm volatile("cp.async.commit_group;" ::: "memory")

#define AS_STRIDE 36
#define BS_STRIDE 136

// ---------------- tf32 mma.sync GEMM: C = A[M,K] @ B[K,N] (+bias)(+act) ----------------
// ACT: 0 none, 1 sigmoid, 2 *g_Wh[row,col], 3 row-scale (1+g_cv[row]),
//      4 also write tf32-rounded copy into g_Whr (N must be 256).
// CAT: 0 normal A; 1 A cols 0..255 from g_attn, 256..511 from g_hs.
template<int ACT, int CAT>
__global__ __launch_bounds__(256, 2) void tgemm_k(const float* __restrict__ A,
                                                  const float* __restrict__ B,
                                                  const float* __restrict__ bias,
                                                  float* __restrict__ C,
                                                  int M, int N, int K)
{
    __shared__ uint32_t As[128*AS_STRIDE];
    __shared__ uint32_t Bs[32*BS_STRIDE];
    const int tid = threadIdx.x;
    const int m0 = blockIdx.y * 128, n0 = blockIdx.x * 128;
    const int wid = tid >> 5, lane = tid & 31;
    const int wm = ((wid >> 2) & 1) * 64;
    const int wn = (wid & 3) * 32;
    const int g = lane >> 2, t = lane & 3;

    const int aRow = tid >> 1, aC16 = (tid & 1) * 16;
    const int bRow = tid >> 3, bC4 = (tid & 7) * 4;
    const float* Ap = A + (size_t)(m0 + aRow) * K + aC16;
    const float* Bp = B + n0 + bC4;

    float acc[4][4][4];
#pragma unroll
    for (int i = 0; i < 4; i++)
#pragma unroll
        for (int j = 0; j < 4; j++)
#pragma unroll
            for (int q = 0; q < 4; q++) acc[i][j][q] = 0.f;

    for (int kt = 0; kt < K; kt += 32) {
        const float* asrc;
        if (CAT == 1) {
            const int cbase = kt + aC16;
            asrc = (cbase < 256)
                 ? g_attn + (size_t)(m0 + aRow) * 256 + cbase
                 : g_hs   + (size_t)(m0 + aRow) * 256 + (cbase - 256);
        } else {
            asrc = Ap + kt;
        }
#pragma unroll
        for (int i = 0; i < 4; i++) {
            float4 v = *(const float4*)(asrc + 4*i);
            uint32_t* d = &As[aRow*AS_STRIDE + aC16 + 4*i];
            d[0] = f2tf32(v.x); d[1] = f2tf32(v.y); d[2] = f2tf32(v.z); d[3] = f2tf32(v.w);
        }
#pragma unroll
        for (int i = 0; i < 4; i++) {
            float4 v = *(const float4*)(Bp + (size_t)(kt + bRow) * N + 32*i);
            uint32_t* d = &Bs[bRow*BS_STRIDE + bC4 + 32*i];
            d[0] = f2tf32(v.x); d[1] = f2tf32(v.y); d[2] = f2tf32(v.z); d[3] = f2tf32(v.w);
        }
        __syncthreads();
#pragma unroll
        for (int ks = 0; ks < 4; ks++) {
            const int kk = ks * 8;
            uint32_t af[4][4], bf[4][2];
#pragma unroll
            for (int mt = 0; mt < 4; mt++) {
                const int r0 = wm + mt*16 + g;
                af[mt][0] = As[r0*AS_STRIDE + kk + t];
                af[mt][1] = As[(r0+8)*AS_STRIDE + kk + t];
                af[mt][2] = As[r0*AS_STRIDE + kk + t + 4];
                af[mt][3] = As[(r0+8)*AS_STRIDE + kk + t + 4];
            }
#pragma unroll
            for (int nt = 0; nt < 4; nt++) {
                const int c = wn + nt*8 + g;
                bf[nt][0] = Bs[(kk+t)*BS_STRIDE + c];
                bf[nt][1] = Bs[(kk+t+4)*BS_STRIDE + c];
            }
#pragma unroll
            for (int mt = 0; mt < 4; mt++)
#pragma unroll
                for (int nt = 0; nt < 4; nt++)
                    mma_tf32(acc[mt][nt], af[mt], bf[nt]);
        }
        __syncthreads();
    }

#pragma unroll
    for (int mt = 0; mt < 4; mt++) {
        const int row = m0 + wm + mt*16 + g;
        float rs0 = 1.f, rs1 = 1.f;
        if (ACT == 3) { rs0 = 1.f + g_cv[row]; rs1 = 1.f + g_cv[row + 8]; }
#pragma unroll
        for (int nt = 0; nt < 4; nt++) {
            const int col = n0 + wn + nt*8 + 2*t;
            float2 bb = make_float2(0.f, 0.f);
            if (bias) bb = *(const float2*)&bias[col];
            float v0 = acc[mt][nt][0] + bb.x, v1 = acc[mt][nt][1] + bb.y;
            float v2 = acc[mt][nt][2] + bb.x, v3 = acc[mt][nt][3] + bb.y;
            if (ACT == 1) {
                v0 = 1.f/(1.f+expf(-v0)); v1 = 1.f/(1.f+expf(-v1));
                v2 = 1.f/(1.f+expf(-v2)); v3 = 1.f/(1.f+expf(-v3));
            }
            if (ACT == 2) {
                const float2 w0 = *(const float2*)&g_Wh[(size_t)row * 256 + col];
                const float2 w1 = *(const float2*)&g_Wh[(size_t)(row + 8) * 256 + col];
                v0 *= w0.x; v1 *= w0.y; v2 *= w1.x; v3 *= w1.y;
            }
            if (ACT == 3) { v0 *= rs0; v1 *= rs0; v2 *= rs1; v3 *= rs1; }
            *(float2*)&C[(size_t)row * N + col]       = make_float2(v0, v1);
            *(float2*)&C[(size_t)(row + 8) * N + col] = make_float2(v2, v3);
            if (ACT == 4) {
                *(float2*)&g_Whr[(size_t)row * N + col] =
                    make_float2(__uint_as_float(f2tf32(v0)), __uint_as_float(f2tf32(v1)));
                *(float2*)&g_Whr[(size_t)(row + 8) * N + col] =
                    make_float2(__uint_as_float(f2tf32(v2)), __uint_as_float(f2tf32(v3)));
            }
        }
    }
}

// ---------------- per-row score vectors ----------------
__global__ __launch_bounds__(256) void rowvec_k(const float* __restrict__ a_src,
                                                const float* __restrict__ a_dst)
{
    const int row = blockIdx.x * 8 + (threadIdx.x >> 5);
    const int lane = threadIdx.x & 31;
    const float* w = g_Wh + (size_t)row * FD;
    float ss = 0.f, dd = 0.f;
#pragma unroll
    for (int c = lane; c < FD; c += 32) {
        float v = w[c];
        ss = fmaf(v, a_src[c], ss);
        dd = fmaf(v, a_dst[c], dd);
    }
#pragma unroll
    for (int o = 16; o; o >>= 1) {
        ss += __shfl_xor_sync(0xffffffffu, ss, o);
        dd += __shfl_xor_sync(0xffffffffu, dd, o);
    }
    if (lane == 0) {
        g_s[row]   = ss;  g_eS[row]  = expf(ss);  g_eS2[row] = expf(0.2f * ss);
        g_dv[row]  = dd;  g_eD[row]  = expf(dd);  g_eD2[row] = expf(0.2f * dd);
    }
}

// ---------------- pipelined attention: BM=128, BN=256, BK=32 ----------------
// A (P) double-buffered via registers; B (Whr) 3-stage cp.async ring.
#define ATT_A_WORDS (128*AS_STRIDE)      // 4608 words / stage
#define ATT_B_STRIDE 264
#define ATT_B_WORDS (32*ATT_B_STRIDE)    // 8448 words / stage
#define ATT_SMEM ((2*ATT_A_WORDS + 3*ATT_B_WORDS) * 4)   // 138240 bytes

__device__ __forceinline__ void issueB(uint32_t bbyte, int row0, int tid) {
#pragma unroll
    for (int r = 0; r < 8; r++) {
        const int idx = tid + r * 256;
        const int row = idx >> 6, c4 = (idx & 63) * 4;
        cpasync16(bbyte + (uint32_t)(row * ATT_B_STRIDE + c4) * 4,
                  g_Whr + (size_t)(row0 + row) * FD + c4);
    }
}

__global__ __launch_bounds__(256, 1) void tattn_k(const int* __restrict__ adj)
{
    extern __shared__ uint32_t sm[];
    uint32_t* Asm = sm;                       // 2 stages
    uint32_t* Bsm = sm + 2*ATT_A_WORDS;       // 3 stages
    const uint32_t bbyte0 = smem_u32(Bsm);
    const int tid = threadIdx.x;
    const int split = blockIdx.x;
    const int i0 = blockIdx.y * 128;
    const int kbeg = split * (NN / KSPLIT);
    const int KT = (NN / KSPLIT) / 32;        // 128
    const int wid = tid >> 5, lane = tid & 31;
    const int wm = (wid >> 2) * 64;
    const int wn = (wid & 3) * 64;
    const int g = lane >> 2, t = lane & 3;

    const int aRow = tid >> 1, aC16 = (tid & 1) * 16;
    const float sv = g_s[i0 + aRow];
    const float ea = g_eS[i0 + aRow];
    const float eb = g_eS2[i0 + aRow];
    const int* adjp = adj + (size_t)(i0 + aRow) * NN + aC16;

    float acc[4][8][4];
#pragma unroll
    for (int i = 0; i < 4; i++)
#pragma unroll
        for (int j = 0; j < 8; j++)
#pragma unroll
            for (int q = 0; q < 4; q++) acc[i][j][q] = 0.f;
    float rsum = 0.f;

    // ---- prologue: B stages 0,1 in flight; A tile 0 into Asm[0] ----
    issueB(bbyte0, kbeg, tid);                     CP_COMMIT();
    issueB(bbyte0 + ATT_B_WORDS*4, kbeg + 32, tid); CP_COMMIT();
    {
        int4 mm[4];
#pragma unroll
        for (int q = 0; q < 4; q++) mm[q] = *(const int4*)(adjp + kbeg + q*4);
        uint32_t* d = Asm + aRow*AS_STRIDE + aC16;
#pragma unroll
        for (int q = 0; q < 4; q++) {
            const int j = kbeg + aC16 + q*4;
            const float4 dj = *(const float4*)&g_dv [j];
            const float4 Ej = *(const float4*)&g_eD [j];
            const float4 Fj = *(const float4*)&g_eD2[j];
            float w0 = mm[q].x ? ((sv + dj.x > 0.f) ? ea*Ej.x : eb*Fj.x) : 0.f;
            float w1 = mm[q].y ? ((sv + dj.y > 0.f) ? ea*Ej.y : eb*Fj.y) : 0.f;
            float w2 = mm[q].z ? ((sv + dj.z > 0.f) ? ea*Ej.z : eb*Fj.z) : 0.f;
            float w3 = mm[q].w ? ((sv + dj.w > 0.f) ? ea*Ej.w : eb*Fj.w) : 0.f;
            uint32_t u0 = f2tf32(w0), u1 = f2tf32(w1), u2 = f2tf32(w2), u3 = f2tf32(w3);
            rsum += (__uint_as_float(u0) + __uint_as_float(u1))
                  + (__uint_as_float(u2) + __uint_as_float(u3));
            *(uint4*)(d + 4*q) = make_uint4(u0, u1, u2, u3);
        }
    }

    int s3 = 0, i3 = 2;
    for (int kt = 0; kt < KT; kt++) {
        const int st2 = kt & 1;
        const bool nx = (kt + 1 < KT);

        // issue B for kt+2 into free ring stage (safe: 3 stages)
        if (kt + 2 < KT) { issueB(bbyte0 + (uint32_t)i3*ATT_B_WORDS*4, kbeg + (kt+2)*32, tid); CP_COMMIT(); }

        // early adj loads for next A tile (DRAM latency hides under MMA)
        int4 mm[4];
        if (nx) {
            const int jb = kbeg + (kt + 1) * 32;
#pragma unroll
            for (int q = 0; q < 4; q++) mm[q] = *(const int4*)(adjp + jb + q*4);
        }

        // B[kt] ready
        if (kt + 2 < KT)      asm volatile("cp.async.wait_group 2;" ::: "memory");
        else if (nx)          asm volatile("cp.async.wait_group 1;" ::: "memory");
        else                  asm volatile("cp.async.wait_group 0;" ::: "memory");
        __syncthreads();

        // ---- MMAs on As[st2], Bs[s3] ----
        {
            const uint32_t* Ac = Asm + st2*ATT_A_WORDS;
            const uint32_t* Bc = Bsm + s3*ATT_B_WORDS;
#pragma unroll
            for (int ks = 0; ks < 4; ks++) {
                const int kk = ks * 8;
                uint32_t af[4][4], bf[8][2];
#pragma unroll
                for (int mt = 0; mt < 4; mt++) {
                    const int r0 = wm + mt*16 + g;
                    af[mt][0] = Ac[r0*AS_STRIDE + kk + t];
                    af[mt][1] = Ac[(r0+8)*AS_STRIDE + kk + t];
                    af[mt][2] = Ac[r0*AS_STRIDE + kk + t + 4];
                    af[mt][3] = Ac[(r0+8)*AS_STRIDE + kk + t + 4];
                }
#pragma unroll
                for (int nt = 0; nt < 8; nt++) {
                    const int c = wn + nt*8 + g;
                    bf[nt][0] = Bc[(kk+t)*ATT_B_STRIDE + c];
                    bf[nt][1] = Bc[(kk+t+4)*ATT_B_STRIDE + c];
                }
#pragma unroll
                for (int mt = 0; mt < 4; mt++)
#pragma unroll
                    for (int nt = 0; nt < 8; nt++)
                        mma_tf32(acc[mt][nt], af[mt], bf[nt]);
            }
        }

        // ---- synthesize + store next A tile into As[st2^1] ----
        if (nx) {
            const int jb = kbeg + (kt + 1) * 32;
            uint32_t* d = Asm + (st2^1)*ATT_A_WORDS + aRow*AS_STRIDE + aC16;
#pragma unroll
            for (int q = 0; q < 4; q++) {
                const int j = jb + aC16 + q*4;
                const float4 dj = *(const float4*)&g_dv [j];
                const float4 Ej = *(const float4*)&g_eD [j];
                const float4 Fj = *(const float4*)&g_eD2[j];
                float w0 = mm[q].x ? ((sv + dj.x > 0.f) ? ea*Ej.x : eb*Fj.x) : 0.f;
                float w1 = mm[q].y ? ((sv + dj.y > 0.f) ? ea*Ej.y : eb*Fj.y) : 0.f;
                float w2 = mm[q].z ? ((sv + dj.z > 0.f) ? ea*Ej.z : eb*Fj.z) : 0.f;
                float w3 = mm[q].w ? ((sv + dj.w > 0.f) ? ea*Ej.w : eb*Fj.w) : 0.f;
                uint32_t u0 = f2tf32(w0), u1 = f2tf32(w1), u2 = f2tf32(w2), u3 = f2tf32(w3);
                rsum += (__uint_as_float(u0) + __uint_as_float(u1))
                      + (__uint_as_float(u2) + __uint_as_float(u3));
                *(uint4*)(d + 4*q) = make_uint4(u0, u1, u2, u3);
            }
        }

        s3 = (s3 == 2) ? 0 : s3 + 1;
        i3 = (i3 == 2) ? 0 : i3 + 1;
    }

    // row sums (lanes tid, tid^1 share aRow)
    rsum += __shfl_xor_sync(0xffffffffu, rsum, 1);
    if ((tid & 1) == 0) g_rsp[split * NN + i0 + aRow] = rsum;

    float* outp = g_attp + (size_t)split * NN * FD;
#pragma unroll
    for (int mt = 0; mt < 4; mt++) {
        const int row = i0 + wm + mt*16 + g;
#pragma unroll
        for (int nt = 0; nt < 8; nt++) {
            const int col = wn + nt*8 + 2*t;
            *(float2*)&outp[(size_t)row * FD + col]       = make_float2(acc[mt][nt][0], acc[mt][nt][1]);
            *(float2*)&outp[(size_t)(row + 8) * FD + col] = make_float2(acc[mt][nt][2], acc[mt][nt][3]);
        }
    }
}

// combine k-splits and normalize
__global__ void attn_comb_k() {
    const size_t idx = (size_t)blockIdx.x * 256 + threadIdx.x;
    const size_t row = idx >> 8;
    float rs = 0.f, v = 0.f;
#pragma unroll
    for (int s = 0; s < KSPLIT; s++) {
        rs += g_rsp[s * NN + row];
        v  += g_attp[(size_t)s * NN * FD + idx];
    }
    g_attn[idx] = v / rs;
}

// ---------------- LayerNorm(512) then SiLU, in place ----------------
__global__ __launch_bounds__(256) void ln_silu_k(float* __restrict__ x,
                                                 const float* __restrict__ g,
                                                 const float* __restrict__ b)
{
    __shared__ float sm1[8], sm2[8];
    const int row = blockIdx.x, tid = threadIdx.x;
    const int lane = tid & 31, wid = tid >> 5;
    float* p = x + (size_t)row * 512;
    float v0 = p[tid], v1 = p[tid + 256];
    float s1 = v0 + v1;
    float s2 = fmaf(v0, v0, v1 * v1);
#pragma unroll
    for (int o = 16; o; o >>= 1) {
        s1 += __shfl_xor_sync(0xffffffffu, s1, o);
        s2 += __shfl_xor_sync(0xffffffffu, s2, o);
    }
    if (lane == 0) { sm1[wid] = s1; sm2[wid] = s2; }
    __syncthreads();
    s1 = 0.f; s2 = 0.f;
#pragma unroll
    for (int i = 0; i < 8; i++) { s1 += sm1[i]; s2 += sm2[i]; }
    const float mean = s1 * (1.f/512.f);
    const float var  = s2 * (1.f/512.f) - mean*mean;
    const float rstd = rsqrtf(var + 1e-5f);
    float y0 = (v0 - mean) * rstd * g[tid]     + b[tid];
    float y1 = (v1 - mean) * rstd * g[tid+256] + b[tid+256];
    p[tid]       = y0 / (1.f + expf(-y0));
    p[tid + 256] = y1 / (1.f + expf(-y1));
}

// ---------------- SSM middle ----------------
__global__ __launch_bounds__(128) void ssm_mid_k(const float* __restrict__ Avec,
                                                 const float* __restrict__ cp_w,
                                                 const float* __restrict__ cp_b)
{
    __shared__ float smx[4], sms[4], smc[4];
    const int row = blockIdx.x, tid = threadIdx.x;
    const int lane = tid & 31, wid = tid >> 5;
    const float* base = g_bcdt + (size_t)row * 384;
    const float Bv = base[tid];
    const float Cv = base[128 + tid];
    float tv = base[256 + tid] + Avec[tid];

    float mx = tv;
#pragma unroll
    for (int o = 16; o; o >>= 1) mx = fmaxf(mx, __shfl_xor_sync(0xffffffffu, mx, o));
    if (lane == 0) smx[wid] = mx;
    __syncthreads();
    mx = fmaxf(fmaxf(smx[0], smx[1]), fmaxf(smx[2], smx[3]));

    const float e = expf(tv - mx);
    float s = e;
    float cd = Cv * cp_w[tid];
#pragma unroll
    for (int o = 16; o; o >>= 1) {
        s  += __shfl_xor_sync(0xffffffffu, s, o);
        cd += __shfl_xor_sync(0xffffffffu, cd, o);
    }
    if (lane == 0) { sms[wid] = s; smc[wid] = cd; }
    __syncthreads();
    const float tot = sms[0] + sms[1] + sms[2] + sms[3];
    g_asmb[(size_t)row * 128 + tid] = (e / tot) * Bv;
    if (tid == 0) g_cv[row] = smc[0] + smc[1] + smc[2] + smc[3] + cp_b[0];
}

// ---------------- hz gate ----------------
__global__ void hz_gate_k(const float* __restrict__ Dp) {
    const size_t idx = (size_t)blockIdx.x * 256 + threadIdx.x;
    const size_t row = idx >> 9, c = idx & 511;
    const float hp = g_hz[row*1024 + c];
    const float z  = g_hz[row*1024 + 512 + c];
    g_u[idx] = hp * (z / (1.f + expf(-z)) + Dp[0]);
}

// ---------------- final fuse + LayerNorm(256) ----------------
__global__ __launch_bounds__(256) void fuse_ln_k(const float* __restrict__ lng,
                                                 const float* __restrict__ lnb,
                                                 float* __restrict__ out)
{
    __shared__ float sm1[8], sm2[8];
    const int row = blockIdx.x, tid = threadIdx.x;
    const int lane = tid & 31, wid = tid >> 5;
    const size_t idx = (size_t)row * 256 + tid;
    const float gg = g_gate[idx];
    const float f = gg * g_attn[idx] + (1.f - gg) * g_hs[idx] + g_enh[idx];
    float s1 = f, s2 = f * f;
#pragma unroll
    for (int o = 16; o; o >>= 1) {
        s1 += __shfl_xor_sync(0xffffffffu, s1, o);
        s2 += __shfl_xor_sync(0xffffffffu, s2, o);
    }
    if (lane == 0) { sm1[wid] = s1; sm2[wid] = s2; }
    __syncthreads();
    s1 = 0.f; s2 = 0.f;
#pragma unroll
    for (int i = 0; i < 8; i++) { s1 += sm1[i]; s2 += sm2[i]; }
    const float mean = s1 * (1.f/256.f);
    const float var  = s2 * (1.f/256.f) - mean*mean;
    const float rstd = rsqrtf(var + 1e-5f);
    out[idx] = (f - mean) * rstd * lng[tid] + lnb[tid];
}

// ---------------- launch ----------------
extern "C" void kernel_launch(void* const* d_in, const int* in_sizes, int n_in,
                              void* d_out, int out_size)
{
    const float* h       = (const float*)d_in[0];
    const int*   adj     = (const int*)  d_in[1];
    const float* W       = (const float*)d_in[2];
    const float* a_src   = (const float*)d_in[3];
    const float* a_dst   = (const float*)d_in[4];
    const float* W_bcdt  = (const float*)d_in[5];
    const float* b_bcdt  = (const float*)d_in[6];
    const float* abp_w   = (const float*)d_in[7];
    const float* abp_b   = (const float*)d_in[8];
    const float* cp_w    = (const float*)d_in[9];
    const float* cp_b    = (const float*)d_in[10];
    const float* W_hz    = (const float*)d_in[11];
    const float* b_hz    = (const float*)d_in[12];
    const float* out_w   = (const float*)d_in[13];
    const float* out_b   = (const float*)d_in[14];
    const float* fe1_w   = (const float*)d_in[15];
    const float* fe1_b   = (const float*)d_in[16];
    const float* fe_ln_g = (const float*)d_in[17];
    const float* fe_ln_b = (const float*)d_in[18];
    const float* fe2_w   = (const float*)d_in[19];
    const float* fe2_b   = (const float*)d_in[20];
    const float* Avec    = (const float*)d_in[21];
    const float* Dp      = (const float*)d_in[22];
    const float* g1_w    = (const float*)d_in[23];
    const float* g1_b    = (const float*)d_in[24];
    const float* g_ln_g  = (const float*)d_in[25];
    const float* g_ln_b  = (const float*)d_in[26];
    const float* g2_w    = (const float*)d_in[27];
    const float* g2_b    = (const float*)d_in[28];
    const float* ln_g    = (const float*)d_in[29];
    const float* ln_b    = (const float*)d_in[30];
    float* out = (float*)d_out;

    void* p;
    cudaGetSymbolAddress(&p, g_Wh);   float* Wh   = (float*)p;
    cudaGetSymbolAddress(&p, g_fe);   float* fe   = (float*)p;
    cudaGetSymbolAddress(&p, g_enh);  float* enh  = (float*)p;
    cudaGetSymbolAddress(&p, g_bcdt); float* bcdt = (float*)p;
    cudaGetSymbolAddress(&p, g_asmb); float* asmb = (float*)p;
    cudaGetSymbolAddress(&p, g_ab);   float* ab   = (float*)p;
    cudaGetSymbolAddress(&p, g_hz);   float* hz   = (float*)p;
    cudaGetSymbolAddress(&p, g_u);    float* u    = (float*)p;
    cudaGetSymbolAddress(&p, g_hs);   float* hs   = (float*)p;
    cudaGetSymbolAddress(&p, g_gt);   float* gt   = (float*)p;
    cudaGetSymbolAddress(&p, g_gate); float* gate = (float*)p;

    cudaFuncSetAttribute(tattn_k, cudaFuncAttributeMaxDynamicSharedMemorySize, ATT_SMEM);

    // 1) Wh = h @ W  (also emits tf32-rounded g_Whr)
    tgemm_k<4,0><<<dim3(FD/128, NN/128), 256>>>(h, W, nullptr, Wh, NN, FD, FD);
    // 2) per-row score vectors
    rowvec_k<<<NN/8, 256>>>(a_src, a_dst);
    // 3) pipelined attention + combine
    tattn_k<<<dim3(KSPLIT, NN/128), 256, ATT_SMEM>>>(adj);
    attn_comb_k<<<NN*FD/256, 256>>>();
    // 4) feature enhancer
    tgemm_k<0,0><<<dim3(512/128, NN/128), 256>>>(Wh, fe1_w, fe1_b, fe, NN, 512, FD);
    ln_silu_k<<<NN, 256>>>(fe, fe_ln_g, fe_ln_b);
    tgemm_k<0,0><<<dim3(FD/128, NN/128), 256>>>(fe, fe2_w, fe2_b, enh, NN, FD, 512);
    // 5) SSM branch
    tgemm_k<0,0><<<dim3(384/128, NN/128), 256>>>(Wh, W_bcdt, b_bcdt, bcdt, NN, 384, FD);
    ssm_mid_k<<<NN, 128>>>(Avec, cp_w, cp_b);
    tgemm_k<2,0><<<dim3(FD/128, NN/128), 256>>>(asmb, abp_w, abp_b, ab, NN, FD, 128);
    tgemm_k<0,0><<<dim3(1024/128, NN/128), 256>>>(ab, W_hz, b_hz, hz, NN, 1024, FD);
    hz_gate_k<<<NN*512/256, 256>>>(Dp);
    tgemm_k<3,0><<<dim3(FD/128, NN/128), 256>>>(u, out_w, out_b, hs, NN, FD, 512);
    // 6) gated fusion + output LN
    tgemm_k<0,1><<<dim3(512/128, NN/128), 256>>>(nullptr, g1_w, g1_b, gt, NN, 512, 512);
    ln_silu_k<<<NN, 256>>>(gt, g_ln_g, g_ln_b);
    tgemm_k<1,0><<<dim3(FD/128, NN/128), 256>>>(gt, g2_w, g2_b, gate, NN, FD, 512);
    fuse_ln_k<<<NN, 256>>>(ln_g, ln_b, out);
}

// round 10
// speedup vs baseline: 1.3500x; 1.3500x over previous
#include <cuda_runtime.h>
#include <math.h>
#include <stdint.h>

#define NN 8192
#define FD 256
#define KSPLIT 2

// ---------------- scratch ----------------
__device__ float g_Wh[NN*FD];
__device__ float g_Whr[NN*FD];     // tf32-rounded Wh (attention B operand, cp.async source)
__device__ float g_s[NN], g_dv[NN], g_eS[NN], g_eS2[NN], g_eD[NN], g_eD2[NN];
__device__ float g_attn[NN*FD];
__device__ float g_attp[KSPLIT*NN*FD];
__device__ float g_rsp[KSPLIT*NN];
__device__ float g_bcdt[NN*384];
__device__ float g_asmb[NN*128];
__device__ float g_cv[NN];
__device__ float g_ab[NN*FD];
__device__ float g_hz[NN*1024];
__device__ float g_u[NN*512];
__device__ float g_hs[NN*FD];
__device__ float g_enh[NN*FD];
__device__ float g_fe[NN*512];
__device__ float g_gt[NN*512];
__device__ float g_gate[NN*FD];

// ---------------- helpers ----------------
__device__ __forceinline__ uint32_t f2tf32(float v) {
    uint32_t r;
    asm("cvt.rna.tf32.f32 %0, %1;" : "=r"(r) : "f"(v));
    return r;
}
__device__ __forceinline__ void mma_tf32(float* c, const uint32_t* a, const uint32_t* b) {
    asm volatile(
        "mma.sync.aligned.m16n8k8.row.col.f32.tf32.tf32.f32 "
        "{%0,%1,%2,%3}, {%4,%5,%6,%7}, {%8,%9}, {%0,%1,%2,%3};"
        : "+f"(c[0]), "+f"(c[1]), "+f"(c[2]), "+f"(c[3])
        : "r"(a[0]), "r"(a[1]), "r"(a[2]), "r"(a[3]), "r"(b[0]), "r"(b[1]));
}
__device__ __forceinline__ uint32_t smem_u32(const void* p) {
    uint32_t a;
    asm("{ .reg .u64 t; cvta.to.shared.u64 t, %1; cvt.u32.u64 %0, t; }" : "=r"(a) : "l"(p));
    return a;
}
__device__ __forceinline__ void cpasync16(uint32_t dst, const void* src) {
    asm volatile("cp.async.cg.shared.global [%0], [%1], 16;" :: "r"(dst), "l"(src));
}
#define CP_COMMIT() asm volatile("cp.async.commit_group;" ::: "memory")

#define AS_STRIDE 36
#define BS_STRIDE 136

// ---------------- tf32 mma.sync GEMM: C = A[M,K] @ B[K,N] (+bias)(+act) ----------------
// ACT: 0 none, 1 sigmoid, 2 *g_Wh[row,col], 3 row-scale (1+g_cv[row]),
//      4 also write tf32-rounded copy into g_Whr (N must be 256).
// CAT: 0 normal A; 1 A cols 0..255 from g_attn, 256..511 from g_hs.
template<int ACT, int CAT>
__global__ __launch_bounds__(256, 2) void tgemm_k(const float* __restrict__ A,
                                                  const float* __restrict__ B,
                                                  const float* __restrict__ bias,
                                                  float* __restrict__ C,
                                                  int M, int N, int K)
{
    __shared__ uint32_t As[128*AS_STRIDE];
    __shared__ uint32_t Bs[32*BS_STRIDE];
    const int tid = threadIdx.x;
    const int m0 = blockIdx.y * 128, n0 = blockIdx.x * 128;
    const int wid = tid >> 5, lane = tid & 31;
    const int wm = ((wid >> 2) & 1) * 64;
    const int wn = (wid & 3) * 32;
    const int g = lane >> 2, t = lane & 3;

    const int aRow = tid >> 1, aC16 = (tid & 1) * 16;
    const int bRow = tid >> 3, bC4 = (tid & 7) * 4;
    const float* Ap = A + (size_t)(m0 + aRow) * K + aC16;
    const float* Bp = B + n0 + bC4;

    float acc[4][4][4];
#pragma unroll
    for (int i = 0; i < 4; i++)
#pragma unroll
        for (int j = 0; j < 4; j++)
#pragma unroll
            for (int q = 0; q < 4; q++) acc[i][j][q] = 0.f;

    for (int kt = 0; kt < K; kt += 32) {
        const float* asrc;
        if (CAT == 1) {
            const int cbase = kt + aC16;
            asrc = (cbase < 256)
                 ? g_attn + (size_t)(m0 + aRow) * 256 + cbase
                 : g_hs   + (size_t)(m0 + aRow) * 256 + (cbase - 256);
        } else {
            asrc = Ap + kt;
        }
#pragma unroll
        for (int i = 0; i < 4; i++) {
            float4 v = *(const float4*)(asrc + 4*i);
            uint32_t* d = &As[aRow*AS_STRIDE + aC16 + 4*i];
            d[0] = f2tf32(v.x); d[1] = f2tf32(v.y); d[2] = f2tf32(v.z); d[3] = f2tf32(v.w);
        }
#pragma unroll
        for (int i = 0; i < 4; i++) {
            float4 v = *(const float4*)(Bp + (size_t)(kt + bRow) * N + 32*i);
            uint32_t* d = &Bs[bRow*BS_STRIDE + bC4 + 32*i];
            d[0] = f2tf32(v.x); d[1] = f2tf32(v.y); d[2] = f2tf32(v.z); d[3] = f2tf32(v.w);
        }
        __syncthreads();
#pragma unroll
        for (int ks = 0; ks < 4; ks++) {
            const int kk = ks * 8;
            uint32_t af[4][4], bf[4][2];
#pragma unroll
            for (int mt = 0; mt < 4; mt++) {
                const int r0 = wm + mt*16 + g;
                af[mt][0] = As[r0*AS_STRIDE + kk + t];
                af[mt][1] = As[(r0+8)*AS_STRIDE + kk + t];
                af[mt][2] = As[r0*AS_STRIDE + kk + t + 4];
                af[mt][3] = As[(r0+8)*AS_STRIDE + kk + t + 4];
            }
#pragma unroll
            for (int nt = 0; nt < 4; nt++) {
                const int c = wn + nt*8 + g;
                bf[nt][0] = Bs[(kk+t)*BS_STRIDE + c];
                bf[nt][1] = Bs[(kk+t+4)*BS_STRIDE + c];
            }
#pragma unroll
            for (int mt = 0; mt < 4; mt++)
#pragma unroll
                for (int nt = 0; nt < 4; nt++)
                    mma_tf32(acc[mt][nt], af[mt], bf[nt]);
        }
        __syncthreads();
    }

#pragma unroll
    for (int mt = 0; mt < 4; mt++) {
        const int row = m0 + wm + mt*16 + g;
        float rs0 = 1.f, rs1 = 1.f;
        if (ACT == 3) { rs0 = 1.f + g_cv[row]; rs1 = 1.f + g_cv[row + 8]; }
#pragma unroll
        for (int nt = 0; nt < 4; nt++) {
            const int col = n0 + wn + nt*8 + 2*t;
            float2 bb = make_float2(0.f, 0.f);
            if (bias) bb = *(const float2*)&bias[col];
            float v0 = acc[mt][nt][0] + bb.x, v1 = acc[mt][nt][1] + bb.y;
            float v2 = acc[mt][nt][2] + bb.x, v3 = acc[mt][nt][3] + bb.y;
            if (ACT == 1) {
                v0 = 1.f/(1.f+expf(-v0)); v1 = 1.f/(1.f+expf(-v1));
                v2 = 1.f/(1.f+expf(-v2)); v3 = 1.f/(1.f+expf(-v3));
            }
            if (ACT == 2) {
                const float2 w0 = *(const float2*)&g_Wh[(size_t)row * 256 + col];
                const float2 w1 = *(const float2*)&g_Wh[(size_t)(row + 8) * 256 + col];
                v0 *= w0.x; v1 *= w0.y; v2 *= w1.x; v3 *= w1.y;
            }
            if (ACT == 3) { v0 *= rs0; v1 *= rs0; v2 *= rs1; v3 *= rs1; }
            *(float2*)&C[(size_t)row * N + col]       = make_float2(v0, v1);
            *(float2*)&C[(size_t)(row + 8) * N + col] = make_float2(v2, v3);
            if (ACT == 4) {
                *(float2*)&g_Whr[(size_t)row * N + col] =
                    make_float2(__uint_as_float(f2tf32(v0)), __uint_as_float(f2tf32(v1)));
                *(float2*)&g_Whr[(size_t)(row + 8) * N + col] =
                    make_float2(__uint_as_float(f2tf32(v2)), __uint_as_float(f2tf32(v3)));
            }
        }
    }
}

// ---------------- per-row score vectors ----------------
__global__ __launch_bounds__(256) void rowvec_k(const float* __restrict__ a_src,
                                                const float* __restrict__ a_dst)
{
    const int row = blockIdx.x * 8 + (threadIdx.x >> 5);
    const int lane = threadIdx.x & 31;
    const float* w = g_Wh + (size_t)row * FD;
    float ss = 0.f, dd = 0.f;
#pragma unroll
    for (int c = lane; c < FD; c += 32) {
        float v = w[c];
        ss = fmaf(v, a_src[c], ss);
        dd = fmaf(v, a_dst[c], dd);
    }
#pragma unroll
    for (int o = 16; o; o >>= 1) {
        ss += __shfl_xor_sync(0xffffffffu, ss, o);
        dd += __shfl_xor_sync(0xffffffffu, dd, o);
    }
    if (lane == 0) {
        g_s[row]   = ss;  g_eS[row]  = expf(ss);  g_eS2[row] = expf(0.2f * ss);
        g_dv[row]  = dd;  g_eD[row]  = expf(dd);  g_eD2[row] = expf(0.2f * dd);
    }
}

// ---------------- pipelined attention: BM=128, BN=256, BK=32 ----------------
// adj + B both staged through 3-deep cp.async rings (no register pipelining).
#define ATT_A_WORDS  (128*AS_STRIDE)      // 4608 words (single buffer, synthesized P)
#define ATT_ADJ_WORDS (128*AS_STRIDE)     // 4608 words / stage (adj ints, stride 36)
#define ATT_B_STRIDE 264
#define ATT_B_WORDS (32*ATT_B_STRIDE)     // 8448 words / stage
#define OFF_ADJ (ATT_A_WORDS)
#define OFF_B   (ATT_A_WORDS + 3*ATT_ADJ_WORDS)
#define ATT_SMEM ((ATT_A_WORDS + 3*ATT_ADJ_WORDS + 3*ATT_B_WORDS) * 4)  // 175104 B

__global__ __launch_bounds__(256, 1) void tattn_k(const int* __restrict__ adj)
{
    extern __shared__ uint32_t sm[];
    uint32_t* Asm = sm;
    const uint32_t adjbyte0 = smem_u32(sm + OFF_ADJ);
    const uint32_t bbyte0   = smem_u32(sm + OFF_B);
    const int tid = threadIdx.x;
    const int split = blockIdx.x;
    const int i0 = blockIdx.y * 128;
    const int kbeg = split * (NN / KSPLIT);
    const int KT = (NN / KSPLIT) / 32;        // 128
    const int wid = tid >> 5, lane = tid & 31;
    const int wm = (wid >> 2) * 64;
    const int wn = (wid & 3) * 64;
    const int g = lane >> 2, t = lane & 3;

    const int aRow = tid >> 1, aC16 = (tid & 1) * 16;
    const float sv = g_s[i0 + aRow];
    const float ea = g_eS[i0 + aRow];
    const float eb = g_eS2[i0 + aRow];

    // cp.async source mappings
    const int adRow = tid >> 3, adC4 = (tid & 7) * 4;      // adj: 128 rows x 8 int4 chunks
    const int bRow = tid >> 6, bC4 = (tid & 63) * 4;       // B: idx-based below

    float acc[4][8][4];
#pragma unroll
    for (int i = 0; i < 4; i++)
#pragma unroll
        for (int j = 0; j < 8; j++)
#pragma unroll
            for (int q = 0; q < 4; q++) acc[i][j][q] = 0.f;
    float rsum = 0.f;

    // ---- issue one (adj+B) group for tile jb into ring stage st ----
    auto issueAdjB = [&](int st, int jb) {
        const uint32_t ad = adjbyte0 + (uint32_t)st * ATT_ADJ_WORDS * 4;
#pragma unroll
        for (int r = 0; r < 4; r++) {
            const int idx = tid + r * 256;                  // 0..1023
            const int row = idx >> 3, c4 = (idx & 7) * 4;
            cpasync16(ad + (uint32_t)(row * AS_STRIDE + c4) * 4,
                      adj + (size_t)(i0 + row) * NN + jb + c4);
        }
        const uint32_t bd = bbyte0 + (uint32_t)st * ATT_B_WORDS * 4;
#pragma unroll
        for (int r = 0; r < 8; r++) {
            const int idx = tid + r * 256;                  // 0..2047
            const int row = idx >> 6, c4 = (idx & 63) * 4;
            cpasync16(bd + (uint32_t)(row * ATT_B_STRIDE + c4) * 4,
                      g_Whr + (size_t)(jb + row) * FD + c4);
        }
        CP_COMMIT();
    };

    // prologue: stages 0,1 in flight
    issueAdjB(0, kbeg);
    issueAdjB(1, kbeg + 32);

    for (int kt = 0; kt < KT; kt++) {
        const int st = kt % 3;

        if (kt + 1 < KT) asm volatile("cp.async.wait_group 1;" ::: "memory");
        else             asm volatile("cp.async.wait_group 0;" ::: "memory");
        __syncthreads();   // all warps past previous MMA + cp.async data visible CTA-wide

        // refill the stage freed at tile kt-1
        if (kt + 2 < KT) issueAdjB((kt + 2) % 3, kbeg + (kt + 2) * 32);

        // ---- synthesize P tile from smem adj -> As ----
        {
            const int jb = kbeg + kt * 32;
            const uint32_t* adjs = sm + OFF_ADJ + st * ATT_ADJ_WORDS;
            uint32_t* d = Asm + aRow*AS_STRIDE + aC16;
#pragma unroll
            for (int q = 0; q < 4; q++) {
                const int4 m = *(const int4*)&adjs[aRow*AS_STRIDE + aC16 + 4*q];
                const int j = jb + aC16 + q*4;
                const float4 dj = *(const float4*)&g_dv [j];
                const float4 Ej = *(const float4*)&g_eD [j];
                const float4 Fj = *(const float4*)&g_eD2[j];
                float w0 = m.x ? ((sv + dj.x > 0.f) ? ea*Ej.x : eb*Fj.x) : 0.f;
                float w1 = m.y ? ((sv + dj.y > 0.f) ? ea*Ej.y : eb*Fj.y) : 0.f;
                float w2 = m.z ? ((sv + dj.z > 0.f) ? ea*Ej.z : eb*Fj.z) : 0.f;
                float w3 = m.w ? ((sv + dj.w > 0.f) ? ea*Ej.w : eb*Fj.w) : 0.f;
                uint32_t u0 = f2tf32(w0), u1 = f2tf32(w1), u2 = f2tf32(w2), u3 = f2tf32(w3);
                rsum += (__uint_as_float(u0) + __uint_as_float(u1))
                      + (__uint_as_float(u2) + __uint_as_float(u3));
                *(uint4*)(d + 4*q) = make_uint4(u0, u1, u2, u3);
            }
        }
        __syncthreads();

        // ---- MMAs on As x B[st] ----
        {
            const uint32_t* Bc = sm + OFF_B + st * ATT_B_WORDS;
#pragma unroll
            for (int ks = 0; ks < 4; ks++) {
                const int kk = ks * 8;
                uint32_t af[4][4], bf[8][2];
#pragma unroll
                for (int mt = 0; mt < 4; mt++) {
                    const int r0 = wm + mt*16 + g;
                    af[mt][0] = Asm[r0*AS_STRIDE + kk + t];
                    af[mt][1] = Asm[(r0+8)*AS_STRIDE + kk + t];
                    af[mt][2] = Asm[r0*AS_STRIDE + kk + t + 4];
                    af[mt][3] = Asm[(r0+8)*AS_STRIDE + kk + t + 4];
                }
#pragma unroll
                for (int nt = 0; nt < 8; nt++) {
                    const int c = wn + nt*8 + g;
                    bf[nt][0] = Bc[(kk+t)*ATT_B_STRIDE + c];
                    bf[nt][1] = Bc[(kk+t+4)*ATT_B_STRIDE + c];
                }
#pragma unroll
                for (int mt = 0; mt < 4; mt++)
#pragma unroll
                    for (int nt = 0; nt < 8; nt++)
                        mma_tf32(acc[mt][nt], af[mt], bf[nt]);
            }
        }
    }

    // row sums (lanes tid, tid^1 share aRow)
    rsum += __shfl_xor_sync(0xffffffffu, rsum, 1);
    if ((tid & 1) == 0) g_rsp[split * NN + i0 + aRow] = rsum;

    float* outp = g_attp + (size_t)split * NN * FD;
#pragma unroll
    for (int mt = 0; mt < 4; mt++) {
        const int row = i0 + wm + mt*16 + g;
#pragma unroll
        for (int nt = 0; nt < 8; nt++) {
            const int col = wn + nt*8 + 2*t;
            *(float2*)&outp[(size_t)row * FD + col]       = make_float2(acc[mt][nt][0], acc[mt][nt][1]);
            *(float2*)&outp[(size_t)(row + 8) * FD + col] = make_float2(acc[mt][nt][2], acc[mt][nt][3]);
        }
    }
}

// combine k-splits and normalize
__global__ void attn_comb_k() {
    const size_t idx = (size_t)blockIdx.x * 256 + threadIdx.x;
    const size_t row = idx >> 8;
    float rs = 0.f, v = 0.f;
#pragma unroll
    for (int s = 0; s < KSPLIT; s++) {
        rs += g_rsp[s * NN + row];
        v  += g_attp[(size_t)s * NN * FD + idx];
    }
    g_attn[idx] = v / rs;
}

// ---------------- LayerNorm(512) then SiLU, in place ----------------
__global__ __launch_bounds__(256) void ln_silu_k(float* __restrict__ x,
                                                 const float* __restrict__ g,
                                                 const float* __restrict__ b)
{
    __shared__ float sm1[8], sm2[8];
    const int row = blockIdx.x, tid = threadIdx.x;
    const int lane = tid & 31, wid = tid >> 5;
    float* p = x + (size_t)row * 512;
    float v0 = p[tid], v1 = p[tid + 256];
    float s1 = v0 + v1;
    float s2 = fmaf(v0, v0, v1 * v1);
#pragma unroll
    for (int o = 16; o; o >>= 1) {
        s1 += __shfl_xor_sync(0xffffffffu, s1, o);
        s2 += __shfl_xor_sync(0xffffffffu, s2, o);
    }
    if (lane == 0) { sm1[wid] = s1; sm2[wid] = s2; }
    __syncthreads();
    s1 = 0.f; s2 = 0.f;
#pragma unroll
    for (int i = 0; i < 8; i++) { s1 += sm1[i]; s2 += sm2[i]; }
    const float mean = s1 * (1.f/512.f);
    const float var  = s2 * (1.f/512.f) - mean*mean;
    const float rstd = rsqrtf(var + 1e-5f);
    float y0 = (v0 - mean) * rstd * g[tid]     + b[tid];
    float y1 = (v1 - mean) * rstd * g[tid+256] + b[tid+256];
    p[tid]       = y0 / (1.f + expf(-y0));
    p[tid + 256] = y1 / (1.f + expf(-y1));
}

// ---------------- SSM middle ----------------
__global__ __launch_bounds__(128) void ssm_mid_k(const float* __restrict__ Avec,
                                                 const float* __restrict__ cp_w,
                                                 const float* __restrict__ cp_b)
{
    __shared__ float smx[4], sms[4], smc[4];
    const int row = blockIdx.x, tid = threadIdx.x;
    const int lane = tid & 31, wid = tid >> 5;
    const float* base = g_bcdt + (size_t)row * 384;
    const float Bv = base[tid];
    const float Cv = base[128 + tid];
    float tv = base[256 + tid] + Avec[tid];

    float mx = tv;
#pragma unroll
    for (int o = 16; o; o >>= 1) mx = fmaxf(mx, __shfl_xor_sync(0xffffffffu, mx, o));
    if (lane == 0) smx[wid] = mx;
    __syncthreads();
    mx = fmaxf(fmaxf(smx[0], smx[1]), fmaxf(smx[2], smx[3]));

    const float e = expf(tv - mx);
    float s = e;
    float cd = Cv * cp_w[tid];
#pragma unroll
    for (int o = 16; o; o >>= 1) {
        s  += __shfl_xor_sync(0xffffffffu, s, o);
        cd += __shfl_xor_sync(0xffffffffu, cd, o);
    }
    if (lane == 0) { sms[wid] = s; smc[wid] = cd; }
    __syncthreads();
    const float tot = sms[0] + sms[1] + sms[2] + sms[3];
    g_asmb[(size_t)row * 128 + tid] = (e / tot) * Bv;
    if (tid == 0) g_cv[row] = smc[0] + smc[1] + smc[2] + smc[3] + cp_b[0];
}

// ---------------- hz gate ----------------
__global__ void hz_gate_k(const float* __restrict__ Dp) {
    const size_t idx = (size_t)blockIdx.x * 256 + threadIdx.x;
    const size_t row = idx >> 9, c = idx & 511;
    const float hp = g_hz[row*1024 + c];
    const float z  = g_hz[row*1024 + 512 + c];
    g_u[idx] = hp * (z / (1.f + expf(-z)) + Dp[0]);
}

// ---------------- final fuse + LayerNorm(256) ----------------
__global__ __launch_bounds__(256) void fuse_ln_k(const float* __restrict__ lng,
                                                 const float* __restrict__ lnb,
                                                 float* __restrict__ out)
{
    __shared__ float sm1[8], sm2[8];
    const int row = blockIdx.x, tid = threadIdx.x;
    const int lane = tid & 31, wid = tid >> 5;
    const size_t idx = (size_t)row * 256 + tid;
    const float gg = g_gate[idx];
    const float f = gg * g_attn[idx] + (1.f - gg) * g_hs[idx] + g_enh[idx];
    float s1 = f, s2 = f * f;
#pragma unroll
    for (int o = 16; o; o >>= 1) {
        s1 += __shfl_xor_sync(0xffffffffu, s1, o);
        s2 += __shfl_xor_sync(0xffffffffu, s2, o);
    }
    if (lane == 0) { sm1[wid] = s1; sm2[wid] = s2; }
    __syncthreads();
    s1 = 0.f; s2 = 0.f;
#pragma unroll
    for (int i = 0; i < 8; i++) { s1 += sm1[i]; s2 += sm2[i]; }
    const float mean = s1 * (1.f/256.f);
    const float var  = s2 * (1.f/256.f) - mean*mean;
    const float rstd = rsqrtf(var + 1e-5f);
    out[idx] = (f - mean) * rstd * lng[tid] + lnb[tid];
}

// ---------------- launch ----------------
extern "C" void kernel_launch(void* const* d_in, const int* in_sizes, int n_in,
                              void* d_out, int out_size)
{
    const float* h       = (const float*)d_in[0];
    const int*   adj     = (const int*)  d_in[1];
    const float* W       = (const float*)d_in[2];
    const float* a_src   = (const float*)d_in[3];
    const float* a_dst   = (const float*)d_in[4];
    const float* W_bcdt  = (const float*)d_in[5];
    const float* b_bcdt  = (const float*)d_in[6];
    const float* abp_w   = (const float*)d_in[7];
    const float* abp_b   = (const float*)d_in[8];
    const float* cp_w    = (const float*)d_in[9];
    const float* cp_b    = (const float*)d_in[10];
    const float* W_hz    = (const float*)d_in[11];
    const float* b_hz    = (const float*)d_in[12];
    const float* out_w   = (const float*)d_in[13];
    const float* out_b   = (const float*)d_in[14];
    const float* fe1_w   = (const float*)d_in[15];
    const float* fe1_b   = (const float*)d_in[16];
    const float* fe_ln_g = (const float*)d_in[17];
    const float* fe_ln_b = (const float*)d_in[18];
    const float* fe2_w   = (const float*)d_in[19];
    const float* fe2_b   = (const float*)d_in[20];
    const float* Avec    = (const float*)d_in[21];
    const float* Dp      = (const float*)d_in[22];
    const float* g1_w    = (const float*)d_in[23];
    const float* g1_b    = (const float*)d_in[24];
    const float* g_ln_g  = (const float*)d_in[25];
    const float* g_ln_b  = (const float*)d_in[26];
    const float* g2_w    = (const float*)d_in[27];
    const float* g2_b    = (const float*)d_in[28];
    const float* ln_g    = (const float*)d_in[29];
    const float* ln_b    = (const float*)d_in[30];
    float* out = (float*)d_out;

    void* p;
    cudaGetSymbolAddress(&p, g_Wh);   float* Wh   = (float*)p;
    cudaGetSymbolAddress(&p, g_fe);   float* fe   = (float*)p;
    cudaGetSymbolAddress(&p, g_enh);  float* enh  = (float*)p;
    cudaGetSymbolAddress(&p, g_bcdt); float* bcdt = (float*)p;
    cudaGetSymbolAddress(&p, g_asmb); float* asmb = (float*)p;
    cudaGetSymbolAddress(&p, g_ab);   float* ab   = (float*)p;
    cudaGetSymbolAddress(&p, g_hz);   float* hz   = (float*)p;
    cudaGetSymbolAddress(&p, g_u);    float* u    = (float*)p;
    cudaGetSymbolAddress(&p, g_hs);   float* hs   = (float*)p;
    cudaGetSymbolAddress(&p, g_gt);   float* gt   = (float*)p;
    cudaGetSymbolAddress(&p, g_gate); float* gate = (float*)p;

    cudaFuncSetAttribute(tattn_k, cudaFuncAttributeMaxDynamicSharedMemorySize, ATT_SMEM);

    // 1) Wh = h @ W  (also emits tf32-rounded g_Whr)
    tgemm_k<4,0><<<dim3(FD/128, NN/128), 256>>>(h, W, nullptr, Wh, NN, FD, FD);
    // 2) per-row score vectors
    rowvec_k<<<NN/8, 256>>>(a_src, a_dst);
    // 3) pipelined attention + combine
    tattn_k<<<dim3(KSPLIT, NN/128), 256, ATT_SMEM>>>(adj);
    attn_comb_k<<<NN*FD/256, 256>>>();
    // 4) feature enhancer
    tgemm_k<0,0><<<dim3(512/128, NN/128), 256>>>(Wh, fe1_w, fe1_b, fe, NN, 512, FD);
    ln_silu_k<<<NN, 256>>>(fe, fe_ln_g, fe_ln_b);
    tgemm_k<0,0><<<dim3(FD/128, NN/128), 256>>>(fe, fe2_w, fe2_b, enh, NN, FD, 512);
    // 5) SSM branch
    tgemm_k<0,0><<<dim3(384/128, NN/128), 256>>>(Wh, W_bcdt, b_bcdt, bcdt, NN, 384, FD);
    ssm_mid_k<<<NN, 128>>>(Avec, cp_w, cp_b);
    tgemm_k<2,0><<<dim3(FD/128, NN/128), 256>>>(asmb, abp_w, abp_b, ab, NN, FD, 128);
    tgemm_k<0,0><<<dim3(1024/128, NN/128), 256>>>(ab, W_hz, b_hz, hz, NN, 1024, FD);
    hz_gate_k<<<NN*512/256, 256>>>(Dp);
    tgemm_k<3,0><<<dim3(FD/128, NN/128), 256>>>(u, out_w, out_b, hs, NN, FD, 512);
    // 6) gated fusion + output LN
    tgemm_k<0,1><<<dim3(512/128, NN/128), 256>>>(nullptr, g1_w, g1_b, gt, NN, 512, 512);
    ln_silu_k<<<NN, 256>>>(gt, g_ln_g, g_ln_b);
    tgemm_k<1,0><<<dim3(FD/128, NN/128), 256>>>(gt, g2_w, g2_b, gate, NN, FD, 512);
    fuse_ln_k<<<NN, 256>>>(ln_g, ln_b, out);
}